// round 3
// baseline (speedup 1.0000x reference)
#include <cuda_runtime.h>
#include <math.h>

#define BB 8
#define AA 64
#define DE 128
#define MM 512
#define DH 64
#define ZD 128

// Scratch (device globals: allocation-free rule)
__device__ float g_dH2[BB * MM];
__device__ float g_logv[BB * MM * DH];

__device__ __forceinline__ float warp_sum(float v) {
#pragma unroll
    for (int o = 16; o > 0; o >>= 1) v += __shfl_xor_sync(0xffffffffu, v, o);
    return v;
}

// ---------------------------------------------------------------------------
// Prologue: per (b,m) compute Poincare dH2 and log-map vector (shared u term).
// One warp per (b,m); lane l owns dims 2l, 2l+1 of dh=64.
// ---------------------------------------------------------------------------
__global__ void __launch_bounds__(256) prologue_kernel(
    const float* __restrict__ currH,   // [B, DH]
    const float* __restrict__ demoH)   // [B*M, DH]
{
    int gw = blockIdx.x * 8 + (threadIdx.x >> 5);
    int l = threadIdx.x & 31;
    if (gw >= BB * MM) return;
    int b = gw >> 9;   // M = 512

    float x0 = currH[b * DH + 2 * l], x1 = currH[b * DH + 2 * l + 1];
    float y0 = demoH[(size_t)gw * DH + 2 * l], y1 = demoH[(size_t)gw * DH + 2 * l + 1];

    const float thr = 1.0f - 1e-5f;
    float x2 = warp_sum(x0 * x0 + x1 * x1);
    float nx = fmaxf(sqrtf(x2), 1e-15f);
    if (nx > thr) { float s = thr / nx; x0 *= s; x1 *= s; x2 *= s * s; }
    float y2 = warp_sum(y0 * y0 + y1 * y1);
    float ny = fmaxf(sqrtf(y2), 1e-15f);
    if (ny > thr) { float s = thr / ny; y0 *= s; y1 *= s; y2 *= s * s; }

    float xy = warp_sum(x0 * y0 + x1 * y1);

    // u = mobius_add(-x, y), c = 1
    float Ac = 1.0f - 2.0f * xy + y2;
    float Bc = 1.0f - x2;
    float den = fmaxf(1.0f - 2.0f * xy + x2 * y2, 1e-15f);
    float inv = 1.0f / den;
    float u0 = (Bc * y0 - Ac * x0) * inv;
    float u1 = (Bc * y1 - Ac * x1) * inv;

    float un2 = warp_sum(u0 * u0 + u1 * u1);
    float un = fmaxf(sqrtf(un2), 1e-15f);
    float arg = fminf(un, 1.0f - 1e-7f);
    float at = atanhf(arg);

    if (l == 0) g_dH2[gw] = 4.0f * at * at;

    float sc = fmaxf(1.0f - x2, 1e-15f) * at / un;
    g_logv[(size_t)gw * DH + 2 * l]     = sc * u0;
    g_logv[(size_t)gw * DH + 2 * l + 1] = sc * u1;
}

// ---------------------------------------------------------------------------
// Main: one CTA per (b,a). 8 warps x 256 threads, 3 CTAs/SM.
// Warp w owns m = w + 8*(4g+k), g<16, k<4 : 64 m per warp.
// Double-buffered register prefetch of demo float4; scores -> smem;
// log-vec aggregation deferred to an L2-resident post-pass.
// ---------------------------------------------------------------------------
__global__ void __launch_bounds__(256, 3) main_kernel(
    const float* __restrict__ curr_rho,  // [B, A, DE]
    const float* __restrict__ currH,     // [B, DH]
    const float* __restrict__ demo_rho,  // [B, M, A, DE]
    const float* __restrict__ We,        // [64, DE]
    const float* __restrict__ Wh,        // [64, DH]
    const float* __restrict__ gamma,     // [ZD]
    const float* __restrict__ beta,      // [ZD]
    float* __restrict__ out)             // [B, A, ZD]
{
    const int bx = blockIdx.x;           // b*AA + a
    const int b = bx >> 6, a = bx & 63;
    const int tid = threadIdx.x;
    const int w = tid >> 5, l = tid & 31;

    __shared__ float s_h2[MM];
    __shared__ float s_sc[MM];
    __shared__ float s_w[MM];
    __shared__ float s_mx[8], s_sm[8];
    __shared__ float s_acce[8][DE];
    __shared__ float s_vpart[4][DH];
    __shared__ float s_eout[DE];
    __shared__ float s_v[DH];
    __shared__ float s_h[DH];
    __shared__ float s_red[8];

    // preload dH2 for this b (512 floats)
    {
        const float2* p = reinterpret_cast<const float2*>(g_dH2 + b * MM);
        reinterpret_cast<float2*>(s_h2)[tid] = p[tid];
    }
    __syncthreads();

    const size_t mstr = (size_t)(AA * DE / 4);  // float4 stride per m
    const float4* dbase = reinterpret_cast<const float4*>(demo_rho)
                          + ((size_t)b * MM * AA + a) * (DE / 4) + l
                          + (size_t)w * mstr;
    const float4 cur = reinterpret_cast<const float4*>(curr_rho)[(size_t)bx * (DE / 4) + l];

    float mx = -3.0e38f, sm = 0.f;
    float4 ae = make_float4(0.f, 0.f, 0.f, 0.f);

    float4 buf[2][4];
#pragma unroll
    for (int k = 0; k < 4; k++) buf[0][k] = dbase[(size_t)(8 * k) * mstr];

    for (int g = 0; g < 16; g++) {
        const int cb = g & 1, nb = cb ^ 1;
        if (g < 15) {
            const float4* np = dbase + (size_t)(32 * (g + 1)) * mstr;
#pragma unroll
            for (int k = 0; k < 4; k++) buf[nb][k] = np[(size_t)(8 * k) * mstr];
        }
        float s[4];
#pragma unroll
        for (int k = 0; k < 4; k++) {
            float4 dm = buf[cb][k];
            float d0 = cur.x - dm.x, d1 = cur.y - dm.y;
            float d2 = cur.z - dm.z, d3 = cur.w - dm.w;
            s[k] = d0 * d0 + d1 * d1 + d2 * d2 + d3 * d3;
        }
#pragma unroll
        for (int o = 16; o > 0; o >>= 1) {
#pragma unroll
            for (int k = 0; k < 4; k++) s[k] += __shfl_xor_sync(0xffffffffu, s[k], o);
        }
#pragma unroll
        for (int k = 0; k < 4; k++) s[k] = -(s[k] + s_h2[w + 8 * (4 * g + k)]);
        if (l == 0) {
#pragma unroll
            for (int k = 0; k < 4; k++) s_sc[w + 8 * (4 * g + k)] = s[k];
        }
        // group-local max, single (rare) rescale -- warp-uniform branch
        float gm = fmaxf(fmaxf(s[0], s[1]), fmaxf(s[2], s[3]));
        if (gm > mx) {
            float c = __expf(mx - gm);
            mx = gm;
            sm *= c; ae.x *= c; ae.y *= c; ae.z *= c; ae.w *= c;
        }
        float p[4];
#pragma unroll
        for (int k = 0; k < 4; k++) p[k] = __expf(s[k] - mx);
        sm += (p[0] + p[1]) + (p[2] + p[3]);
#pragma unroll
        for (int k = 0; k < 4; k++) {
            float4 dm = buf[cb][k];
            ae.x += p[k] * dm.x; ae.y += p[k] * dm.y;
            ae.z += p[k] * dm.z; ae.w += p[k] * dm.w;
        }
    }

    if (l == 0) { s_mx[w] = mx; s_sm[w] = sm; }
    *reinterpret_cast<float4*>(&s_acce[w][4 * l]) = ae;
    __syncthreads();

    // merge 8 partial softmax states (all threads, redundant, cheap)
    float gmax = -3.0e38f;
#pragma unroll
    for (int q = 0; q < 8; q++) gmax = fmaxf(gmax, s_mx[q]);
    float S = 0.f;
#pragma unroll
    for (int q = 0; q < 8; q++) S += __expf(s_mx[q] - gmax) * s_sm[q];
    float invS = 1.0f / S;

    // un-normalized weights for the v-pass
    s_w[tid]       = __expf(s_sc[tid] - gmax);
    s_w[tid + 256] = __expf(s_sc[tid + 256] - gmax);

    if (tid < DE) {
        float e = 0.f;
#pragma unroll
        for (int q = 0; q < 8; q++) e += __expf(s_mx[q] - gmax) * s_acce[q][tid];
        s_eout[tid] = e * invS;
    }
    __syncthreads();

    // v-pass: v[d] = invS * sum_m w[m] * logv[m][d]   (L2-resident reads)
    {
        int d = tid & 63, q = tid >> 6;   // q in 0..3, 128 m each
        const float* lvp = g_logv + ((size_t)b * MM + q * 128) * DH + d;
        float acc0 = 0.f, acc1 = 0.f;
#pragma unroll 8
        for (int m = 0; m < 128; m += 2) {
            acc0 += s_w[q * 128 + m]     * lvp[(size_t)m * DH];
            acc1 += s_w[q * 128 + m + 1] * lvp[(size_t)(m + 1) * DH];
        }
        s_vpart[q][d] = acc0 + acc1;
    }
    __syncthreads();
    if (tid < DH)
        s_v[tid] = (s_vpart[0][tid] + s_vpart[1][tid] + s_vpart[2][tid] + s_vpart[3][tid]) * invS;
    __syncthreads();

    // exp-map on warp 0 (lane l owns dims 2l, 2l+1)
    if (w == 0) {
        float x0 = currH[b * DH + 2 * l], x1 = currH[b * DH + 2 * l + 1];
        const float thr = 1.0f - 1e-5f;
        float x2 = warp_sum(x0 * x0 + x1 * x1);
        float nx = fmaxf(sqrtf(x2), 1e-15f);
        if (nx > thr) { float s0 = thr / nx; x0 *= s0; x1 *= s0; x2 *= s0 * s0; }
        float lam = 2.0f / fmaxf(1.0f - x2, 1e-15f);

        float v0 = s_v[2 * l], v1 = s_v[2 * l + 1];
        float vn2 = warp_sum(v0 * v0 + v1 * v1);
        float vn = fmaxf(sqrtf(vn2), 1e-15f);
        float fac = tanhf(lam * vn * 0.5f);
        float iv = fac / vn;
        float y0 = v0 * iv, y1 = v1 * iv;

        float yn2 = warp_sum(y0 * y0 + y1 * y1);
        float yn = fmaxf(sqrtf(yn2), 1e-15f);
        if (yn > thr) { float s0 = thr / yn; y0 *= s0; y1 *= s0; yn2 *= s0 * s0; }

        float xy = warp_sum(x0 * y0 + x1 * y1);
        float den = fmaxf(1.0f + 2.0f * xy + x2 * yn2, 1e-15f);
        float ca = (1.0f + 2.0f * xy + yn2) / den;
        float cb2 = (1.0f - x2) / den;
        float o0 = ca * x0 + cb2 * y0, o1 = ca * x1 + cb2 * y1;

        float on2 = warp_sum(o0 * o0 + o1 * o1);
        float on = fmaxf(sqrtf(on2), 1e-15f);
        if (on > thr) { float s0 = thr / on; o0 *= s0; o1 *= s0; }
        s_h[2 * l] = o0; s_h[2 * l + 1] = o1;
    }
    __syncthreads();

    // GEMVs + LayerNorm (threads 0..127 produce z[j]; warps 0..3)
    float zj = 0.f;
    if (tid < ZD) {
        if (tid < 64) {
            const float* wr = We + tid * DE;
#pragma unroll 8
            for (int d = 0; d < DE; d++) zj += wr[d] * s_eout[d];
        } else {
            const float* wr = Wh + (tid - 64) * DH;
#pragma unroll 8
            for (int d = 0; d < DH; d++) zj += wr[d] * s_h[d];
        }
        float p1 = warp_sum(zj);
        float p2 = warp_sum(zj * zj);
        if (l == 0) { s_red[w] = p1; s_red[4 + w] = p2; }
    }
    __syncthreads();
    if (tid < ZD) {
        float sum = s_red[0] + s_red[1] + s_red[2] + s_red[3];
        float sq  = s_red[4] + s_red[5] + s_red[6] + s_red[7];
        float mean = sum * (1.0f / ZD);
        float var = sq * (1.0f / ZD) - mean * mean;
        float r = rsqrtf(var + 1e-5f);
        out[(size_t)bx * ZD + tid] = (zj - mean) * r * gamma[tid] + beta[tid];
    }
}

extern "C" void kernel_launch(void* const* d_in, const int* in_sizes, int n_in,
                              void* d_out, int out_size) {
    const float* curr_rho = (const float*)d_in[0];
    const float* currH    = (const float*)d_in[1];
    const float* demo_rho = (const float*)d_in[2];
    const float* demoH    = (const float*)d_in[3];
    const float* We       = (const float*)d_in[4];
    const float* Wh       = (const float*)d_in[5];
    const float* gamma    = (const float*)d_in[6];
    const float* beta     = (const float*)d_in[7];
    float* out = (float*)d_out;

    prologue_kernel<<<512, 256>>>(currH, demoH);
    main_kernel<<<BB * AA, 256>>>(curr_rho, currH, demo_rho, We, Wh, gamma, beta, out);
}